// round 16
// baseline (speedup 1.0000x reference)
#include <cuda_runtime.h>

#define NSEG 256
#define D 128
#define OUT_ELEMS (NSEG * D)

#define BLOCKS 1184                  // 148 SMs x 8 CTAs, one full wave
#define THREADS 256
#define NWARPS (BLOCKS * (THREADS / 32))   // 9472

// Per-segment counts (alloc-free rule: __device__ global). Zeroed each call
// by a cudaMemsetAsync node in kernel_launch.
__device__ int g_counts[NSEG];

// ---------------------------------------------------------------------------
// Pass 1: segmented sum, atomically accumulated straight into d_out (zeroed
// by a memset node). One warp owns a contiguous row chunk; lane l holds
// float4 columns [4l, 4l+4). Sorted ids: if the chunk's first and last ids
// match, the whole chunk is one segment -> pure streaming quad loop (proven
// body; ~85us with the inline atomic tail, the cheapest measured merge).
// ---------------------------------------------------------------------------
__device__ __forceinline__ void flush_acc(float* __restrict__ out, int seg_id,
                                          int lane, const float4& acc, int cnt) {
    float* p = out + seg_id * D + lane * 4;
    atomicAdd(p + 0, acc.x);
    atomicAdd(p + 1, acc.y);
    atomicAdd(p + 2, acc.z);
    atomicAdd(p + 3, acc.w);
    if (lane == 0) atomicAdd(&g_counts[seg_id], cnt);
}

__global__ __launch_bounds__(THREADS, 8) void segsum_kernel(
    const float4* __restrict__ inp,   // (n, 32) float4 view of (n, 128) float
    const int* __restrict__ seg,      // (n,) sorted segment ids
    float* __restrict__ out,          // (256, 128) running sums (pre-zeroed)
    int n)
{
    const int lane = threadIdx.x & 31;
    const int warp_global = (blockIdx.x * blockDim.x + threadIdx.x) >> 5;

    const int rows_per_warp = (n + NWARPS - 1) / NWARPS;
    const int r0 = warp_global * rows_per_warp;
    const int r1 = min(n, r0 + rows_per_warp);
    if (r0 >= r1) return;
    int r = r0;

    const int first = seg[r0];
    const int last = seg[r1 - 1];

    float4 acc = make_float4(0.0f, 0.0f, 0.0f, 0.0f);

    if (first == last) {
        // -------- Uniform chunk (common case): streaming quad loop. ---------
        while (r + 4 <= r1) {
            float4 v0 = inp[(size_t)(r + 0) * 32 + lane];
            float4 v1 = inp[(size_t)(r + 1) * 32 + lane];
            float4 v2 = inp[(size_t)(r + 2) * 32 + lane];
            float4 v3 = inp[(size_t)(r + 3) * 32 + lane];
            acc.x += (v0.x + v1.x) + (v2.x + v3.x);
            acc.y += (v0.y + v1.y) + (v2.y + v3.y);
            acc.z += (v0.z + v1.z) + (v2.z + v3.z);
            acc.w += (v0.w + v1.w) + (v2.w + v3.w);
            r += 4;
        }
        for (; r < r1; ++r) {
            float4 v = inp[(size_t)r * 32 + lane];
            acc.x += v.x; acc.y += v.y; acc.z += v.z; acc.w += v.w;
        }
        flush_acc(out, first, lane, acc, r1 - r0);
    } else {
        // -------- Boundary chunk (rare, ~3% of warps). ----------------------
        int cnt = 0;
        int cur = first;
        while (r + 4 <= r1) {
            int s0 = seg[r];
            int s3 = seg[r + 3];
            float4 v0 = inp[(size_t)(r + 0) * 32 + lane];
            float4 v1 = inp[(size_t)(r + 1) * 32 + lane];
            float4 v2 = inp[(size_t)(r + 2) * 32 + lane];
            float4 v3 = inp[(size_t)(r + 3) * 32 + lane];
            if (s0 == cur && s3 == cur) {
                acc.x += (v0.x + v1.x) + (v2.x + v3.x);
                acc.y += (v0.y + v1.y) + (v2.y + v3.y);
                acc.z += (v0.z + v1.z) + (v2.z + v3.z);
                acc.w += (v0.w + v1.w) + (v2.w + v3.w);
                cnt += 4;
            } else {
                int s1 = seg[r + 1];
                int s2 = seg[r + 2];
                int   ss[4] = {s0, s1, s2, s3};
                float4 vv[4] = {v0, v1, v2, v3};
                #pragma unroll
                for (int i = 0; i < 4; ++i) {
                    if (ss[i] != cur) {
                        flush_acc(out, cur, lane, acc, cnt);
                        acc = make_float4(0.0f, 0.0f, 0.0f, 0.0f);
                        cnt = 0;
                        cur = ss[i];
                    }
                    acc.x += vv[i].x; acc.y += vv[i].y;
                    acc.z += vv[i].z; acc.w += vv[i].w;
                    cnt++;
                }
            }
            r += 4;
        }
        for (; r < r1; ++r) {
            int s = seg[r];
            float4 v = inp[(size_t)r * 32 + lane];
            if (s != cur) {
                flush_acc(out, cur, lane, acc, cnt);
                acc = make_float4(0.0f, 0.0f, 0.0f, 0.0f);
                cnt = 0;
                cur = s;
            }
            acc.x += v.x; acc.y += v.y; acc.z += v.z; acc.w += v.w;
            cnt++;
        }
        flush_acc(out, cur, lane, acc, cnt);
    }
}

// ---------------------------------------------------------------------------
// Pass 2: divide sums by counts in place (L2-hot; measured ~3.8us in R6).
// ---------------------------------------------------------------------------
__global__ void finalize_kernel(float* __restrict__ out) {
    int i = blockIdx.x * blockDim.x + threadIdx.x;
    if (i >= OUT_ELEMS) return;
    int s = i >> 7;  // / D
    int c = g_counts[s];
    if (c < 1) c = 1;
    out[i] = out[i] / (float)c;
}

// ---------------------------------------------------------------------------
// Launch. d_in[0] = inp (float32, n*128), d_in[1] = batch_seg (int32, n).
// Output: (256, 128) float32 means. Memset nodes replace the 4.1us zero
// kernel (graph-capturable, no kernel-launch floor); then 2 kernels.
// ---------------------------------------------------------------------------
extern "C" void kernel_launch(void* const* d_in, const int* in_sizes, int n_in,
                              void* d_out, int out_size) {
    const float* inp = (const float*)d_in[0];
    const int* seg = (const int*)d_in[1];
    float* out = (float*)d_out;
    const int n = in_sizes[1];  // number of rows

    // Zero the output sums and counts via memset nodes (capture-safe, cheap).
    cudaMemsetAsync(out, 0, OUT_ELEMS * sizeof(float));
    void* counts_ptr = nullptr;
    cudaGetSymbolAddress(&counts_ptr, g_counts);
    cudaMemsetAsync(counts_ptr, 0, NSEG * sizeof(int));

    segsum_kernel<<<BLOCKS, THREADS>>>((const float4*)inp, seg, out, n);
    finalize_kernel<<<(OUT_ELEMS + 255) / 256, 256>>>(out);
}